// round 12
// baseline (speedup 1.0000x reference)
#include <cuda_runtime.h>
#include <cstdint>

#define T_STEPS 512
#define BATCH   512
#define HID     128
#define ACT     18
#define TBROWS  (T_STEPS * BATCH)   // 262144

// Scratch (device globals: allocation is forbidden)
__device__ float g_ys[(size_t)TBROWS * HID];         // ys
__device__ float g_gi [(size_t)TBROWS * 3 * HID];    // gi

typedef unsigned long long u64;

__device__ __forceinline__ u64 pk2(float x) {
    u64 d; asm("mov.b64 %0, {%1,%1};" : "=l"(d) : "f"(x)); return d;
}
__device__ __forceinline__ u64 pk2two(float a, float b) {
    u64 d; asm("mov.b64 %0, {%1,%2};" : "=l"(d) : "f"(a), "f"(b)); return d;
}
__device__ __forceinline__ void fma2(u64 &c, u64 a, u64 b) {
    asm("fma.rn.f32x2 %0, %1, %2, %3;" : "=l"(c) : "l"(a), "l"(b), "l"(c));
}
__device__ __forceinline__ u64 mul2(u64 a, u64 b) {
    u64 d; asm("mul.rn.f32x2 %0, %1, %2;" : "=l"(d) : "l"(a), "l"(b)); return d;
}
__device__ __forceinline__ float2 unpk(u64 v) {
    float2 f; asm("mov.b64 {%0,%1}, %2;" : "=f"(f.x), "=f"(f.y) : "l"(v)); return f;
}
__device__ __forceinline__ void cp_async16(uint32_t dst, const void* src) {
    asm volatile("cp.async.ca.shared.global [%0], [%1], 16;" :: "r"(dst), "l"(src));
}

// ---------------------------------------------------------------------------
// 8x8-per-thread accumulation over K=128 from As[64][132] / Bs[128][128].
// ---------------------------------------------------------------------------
__device__ __forceinline__ void mm8x8_k128(
    const float* __restrict__ As, const float* __restrict__ Bs,
    int tx, int ty, u64 acc[8][4])
{
    #pragma unroll
    for (int r = 0; r < 8; ++r)
        #pragma unroll
        for (int c = 0; c < 4; ++c) acc[r][c] = 0ull;

    const float* ap = As + ty * 8 * 132;
    const u64*   bp = (const u64*)Bs + tx * 4;   // row stride 64 u64

    #pragma unroll
    for (int k4 = 0; k4 < 128; k4 += 4) {
        float4 av[8];
        #pragma unroll
        for (int r = 0; r < 8; ++r)
            av[r] = *(const float4*)(ap + r * 132 + k4);
        #pragma unroll
        for (int kk = 0; kk < 4; ++kk) {
            ulonglong2 b01 = *(const ulonglong2*)(bp + (size_t)(k4 + kk) * 64);
            ulonglong2 b23 = *(const ulonglong2*)(bp + (size_t)(k4 + kk) * 64 + 2);
            #pragma unroll
            for (int r = 0; r < 8; ++r) {
                u64 ad = pk2(((const float*)&av[r])[kk]);
                fma2(acc[r][0], ad, b01.x);
                fma2(acc[r][1], ad, b01.y);
                fma2(acc[r][2], ad, b23.x);
                fma2(acc[r][3], ad, b23.y);
            }
        }
    }
}

// ---------------------------------------------------------------------------
// Fused: emb = relu(obs@W_emb + b_emb) kept on-chip; gi = emb@Wi + bi.
// CTA tile = 64 rows. As buffer holds obs, then is overwritten with emb.
// Bs holds W_emb, then the three 128-col Wi chunks.
// ---------------------------------------------------------------------------
__global__ __launch_bounds__(128, 2) void gemm_fused(
    const float* __restrict__ obs, const float* __restrict__ W_emb,
    const float* __restrict__ b_emb, const float* __restrict__ Wi,
    const float* __restrict__ bi, float* __restrict__ gi)
{
    extern __shared__ float sm[];
    float* As = sm;             // [64][132]
    float* Bs = sm + 64 * 132;  // [128][128]

    const int m0  = blockIdx.x * 64;
    const int tid = threadIdx.x;
    const int tx  = tid & 15;
    const int ty  = tid >> 4;

    // obs tile -> As, W_emb -> Bs
    for (int i = tid; i < 2048; i += 128) {
        int m = i >> 5, kv = (i & 31) << 2;
        *(float4*)(As + m * 132 + kv) =
            *(const float4*)(obs + (size_t)(m0 + m) * 128 + kv);
    }
    for (int i = tid; i < 4096; i += 128) {
        int k = i >> 5, nv = (i & 31) << 2;
        *(float4*)(Bs + k * 128 + nv) =
            *(const float4*)(W_emb + (size_t)k * 128 + nv);
    }
    __syncthreads();

    // emb tile in registers
    float ev[8][8];
    {
        u64 acc[8][4];
        mm8x8_k128(As, Bs, tx, ty, acc);
        float bb[8];
        float4 b0 = *(const float4*)(b_emb + tx * 8);
        float4 b1 = *(const float4*)(b_emb + tx * 8 + 4);
        bb[0]=b0.x; bb[1]=b0.y; bb[2]=b0.z; bb[3]=b0.w;
        bb[4]=b1.x; bb[5]=b1.y; bb[6]=b1.z; bb[7]=b1.w;
        #pragma unroll
        for (int r = 0; r < 8; ++r) {
            float2 f0 = unpk(acc[r][0]), f1 = unpk(acc[r][1]);
            float2 f2 = unpk(acc[r][2]), f3 = unpk(acc[r][3]);
            float v[8] = { f0.x, f0.y, f1.x, f1.y, f2.x, f2.y, f3.x, f3.y };
            #pragma unroll
            for (int j = 0; j < 8; ++j)
                ev[r][j] = fmaxf(v[j] + bb[j], 0.0f);
        }
    }
    __syncthreads();           // all As(obs)/Bs(W_emb) reads done

    // emb -> As (row-major, cols tx*8..+7 for rows ty*8..+7)
    #pragma unroll
    for (int r = 0; r < 8; ++r) {
        *(float4*)(As + (ty * 8 + r) * 132 + tx * 8) =
            make_float4(ev[r][0], ev[r][1], ev[r][2], ev[r][3]);
        *(float4*)(As + (ty * 8 + r) * 132 + tx * 8 + 4) =
            make_float4(ev[r][4], ev[r][5], ev[r][6], ev[r][7]);
    }
    __syncthreads();

    // gi chunks: Bs <- Wi[:, ch*128 ..), compute, store
    for (int ch = 0; ch < 3; ++ch) {
        for (int i = tid; i < 4096; i += 128) {
            int k = i >> 5, nv = (i & 31) << 2;
            *(float4*)(Bs + k * 128 + nv) =
                *(const float4*)(Wi + (size_t)k * 384 + ch * 128 + nv);
        }
        __syncthreads();

        u64 acc[8][4];
        mm8x8_k128(As, Bs, tx, ty, acc);

        float bb[8];
        float4 b0 = *(const float4*)(bi + ch * 128 + tx * 8);
        float4 b1 = *(const float4*)(bi + ch * 128 + tx * 8 + 4);
        bb[0]=b0.x; bb[1]=b0.y; bb[2]=b0.z; bb[3]=b0.w;
        bb[4]=b1.x; bb[5]=b1.y; bb[6]=b1.z; bb[7]=b1.w;
        #pragma unroll
        for (int r = 0; r < 8; ++r) {
            float2 f0 = unpk(acc[r][0]), f1 = unpk(acc[r][1]);
            float2 f2 = unpk(acc[r][2]), f3 = unpk(acc[r][3]);
            float v[8] = { f0.x, f0.y, f1.x, f1.y, f2.x, f2.y, f3.x, f3.y };
            float* cp = gi + (size_t)(m0 + ty * 8 + r) * 384 + ch * 128 + tx * 8;
            *(float4*)(cp)     = make_float4(v[0]+bb[0], v[1]+bb[1], v[2]+bb[2], v[3]+bb[3]);
            *(float4*)(cp + 4) = make_float4(v[4]+bb[4], v[5]+bb[5], v[6]+bb[6], v[7]+bb[7]);
        }
        if (ch < 2) __syncthreads();   // Bs reads done before next overwrite
    }
}

// ---------------------------------------------------------------------------
// Scan: 128 CTAs x 384 threads, 4 batch rows per CTA (R11 — unchanged).
// ---------------------------------------------------------------------------
__device__ __forceinline__ float sigf(float x) {
    return __fdividef(1.0f, 1.0f + __expf(-x));
}
__device__ __forceinline__ float tanhfast(float x) {
    return __fdividef(2.0f, 1.0f + __expf(-2.0f * x)) - 1.0f;
}

__global__ __launch_bounds__(384, 1) void scan_kernel(
    const float* __restrict__ hidden, const float* __restrict__ gi_all,
    const int* __restrict__ dones,
    const float* __restrict__ Wh, const float* __restrict__ bhn,
    float* __restrict__ hfinal, float* __restrict__ ys)
{
    __shared__ float4 h4_s[128];
    __shared__ u64    gh01_s[384];
    __shared__ u64    gh23_s[384];
    __shared__ u64    bhn2_s[128];
    __shared__ u64    maskp_s[T_STEPS * 2];
    __shared__ float  gi_s[2][1536];

    const int tid = threadIdx.x;
    const int b0  = blockIdx.x * 4;

    const uint32_t gi_smem = (uint32_t)__cvta_generic_to_shared(&gi_s[0][0])
                             + (uint32_t)tid * 16u;
    const float* gi_src = gi_all + (size_t)b0 * 384 + tid * 4;

    cp_async16(gi_smem, gi_src);
    asm volatile("cp.async.commit_group;");

    float w[128];
    #pragma unroll
    for (int k = 0; k < 128; ++k)
        w[k] = Wh[(size_t)k * 384 + tid];

    if (tid < 128) bhn2_s[tid] = pk2(bhn[tid]);
    for (int i = tid; i < T_STEPS * 2; i += 384) {
        int t = i >> 1, p = i & 1;
        float m0_ = dones[t * BATCH + b0 + 2 * p]     ? 0.0f : 1.0f;
        float m1_ = dones[t * BATCH + b0 + 2 * p + 1] ? 0.0f : 1.0f;
        maskp_s[i] = pk2two(m0_, m1_);
    }
    for (int idx = tid; idx < 512; idx += 384) {
        int r = idx >> 7, i = idx & 127;
        ((float*)&h4_s[i])[r] = hidden[(size_t)(b0 + r) * 128 + i];
    }
    __syncthreads();

    const u64 NEG1 = pk2two(-1.0f, -1.0f);

    for (int t = 0; t < T_STEPS; ++t) {
        if (t + 1 < T_STEPS) {
            cp_async16(gi_smem + (((t + 1) & 1) ? 6144u : 0u),
                       gi_src + (size_t)(t + 1) * (BATCH * 384));
            asm volatile("cp.async.commit_group;");
        }

        u64 a01 = 0ull, a23 = 0ull;
        #pragma unroll
        for (int k = 0; k < 128; ++k) {
            ulonglong2 hv = *(const ulonglong2*)&h4_s[k];
            u64 wd = pk2(w[k]);
            fma2(a01, hv.x, wd);
            fma2(a23, hv.y, wd);
        }
        gh01_s[tid] = a01;
        gh23_s[tid] = a23;

        if (t + 1 < T_STEPS) {
            asm volatile("cp.async.wait_group 1;");
        } else {
            asm volatile("cp.async.wait_group 0;");
        }
        __syncthreads();   // (A)

        if (tid < 256) {
            const int p = tid >> 7;
            const int i = tid & 127;
            const u64* ghb = p ? gh23_s : gh01_s;
            const u64 mkp = maskp_s[t * 2 + p];

            u64 ghr = ghb[i];
            u64 ghz = ghb[128 + i];
            u64 ghn = ghb[256 + i];

            const float* gb0 = gi_s[t & 1] + (2 * p) * 384;
            const float* gb1 = gb0 + 384;
            u64 xr = pk2two(gb0[i],       gb1[i]);        fma2(xr, ghr, mkp);
            u64 xz = pk2two(gb0[128 + i], gb1[128 + i]);  fma2(xz, ghz, mkp);
            u64 gn = pk2two(gb0[256 + i], gb1[256 + i]);
            u64 t0 = bhn2_s[i];                           fma2(t0, ghn, mkp);

            float2 fr = unpk(xr);
            float2 fz = unpk(xz);
            u64 rp = pk2two(sigf(fr.x), sigf(fr.y));
            u64 zp = pk2two(sigf(fz.x), sigf(fz.y));

            u64 xn = gn; fma2(xn, rp, t0);
            float2 fn = unpk(xn);
            u64 np = pk2two(tanhfast(fn.x), tanhfast(fn.y));

            u64* hp = (u64*)(((char*)&h4_s[i]) + p * 8);
            u64 hm = mul2(*hp, mkp);
            u64 d  = hm; fma2(d, np, NEG1);
            u64 hn = np; fma2(hn, zp, d);
            *hp = hn;

            float2 fh = unpk(hn);
            float* yp = ys + ((size_t)t * BATCH + b0 + 2 * p) * 128 + i;
            yp[0]   = fh.x;
            yp[128] = fh.y;
        }
        __syncthreads();   // (B)
    }

    for (int idx = tid; idx < 512; idx += 384) {
        int r = idx >> 7, i = idx & 127;
        hfinal[(size_t)(b0 + r) * 128 + i] = ((float*)&h4_s[i])[r];
    }
}

// ---------------------------------------------------------------------------
// q projection (clock canary — byte-identical to R4/R11).
// ---------------------------------------------------------------------------
__global__ __launch_bounds__(128, 2) void qproj_kernel(
    const float* __restrict__ ys, const float* __restrict__ Wo,
    const float* __restrict__ bo, float* __restrict__ q)
{
    extern __shared__ float sm[];
    float* As   = sm;                 // [128][129]
    float* Wo_s = sm + 128 * 129;     // [128][20]
    float* bo_s = Wo_s + 128 * 20;    // [18]

    const int tid = threadIdx.x;
    const size_t m0 = (size_t)blockIdx.x * 128;

    for (int i = tid; i < 4096; i += 128) {
        int m = i >> 5, kv = (i & 31) << 2;
        float4 v = *(const float4*)(ys + (m0 + m) * 128 + kv);
        float* d = As + m * 129 + kv;
        d[0] = v.x; d[1] = v.y; d[2] = v.z; d[3] = v.w;
    }
    for (int i = tid; i < 128 * 18; i += 128)
        Wo_s[(i / 18) * 20 + (i % 18)] = Wo[i];
    if (tid < 18) bo_s[tid] = bo[tid];
    __syncthreads();

    u64 acc[9];
    #pragma unroll
    for (int p = 0; p < 9; ++p) acc[p] = pk2two(bo_s[2 * p], bo_s[2 * p + 1]);

    const float* ap = As + tid * 129;
    #pragma unroll 4
    for (int k = 0; k < 128; ++k) {
        u64 hd = pk2(ap[k]);
        const u64* wrow = (const u64*)(Wo_s + k * 20);
        #pragma unroll
        for (int p = 0; p < 9; ++p) fma2(acc[p], hd, wrow[p]);
    }

    float* qp = q + (m0 + tid) * ACT;
    #pragma unroll
    for (int p = 0; p < 9; ++p) {
        float2 f = unpk(acc[p]);
        *(float2*)(qp + 2 * p) = f;
    }
}

// ---------------------------------------------------------------------------
extern "C" void kernel_launch(void* const* d_in, const int* in_sizes, int n_in,
                              void* d_out, int out_size)
{
    const float* hidden = (const float*)d_in[0];
    const float* obs    = (const float*)d_in[1];
    const int*   dones  = (const int*)d_in[2];
    const float* W_emb  = (const float*)d_in[3];
    const float* b_emb  = (const float*)d_in[4];
    const float* Wi     = (const float*)d_in[5];
    const float* bi     = (const float*)d_in[6];
    const float* Wh     = (const float*)d_in[7];
    const float* bhn    = (const float*)d_in[8];
    const float* W_out  = (const float*)d_in[9];
    const float* b_out  = (const float*)d_in[10];

    float* out    = (float*)d_out;
    float* hfinal = out;                        // [512, 128]
    float* q      = out + (size_t)BATCH * HID;  // [512, 512, 18]

    void *p_ys, *p_gi;
    cudaGetSymbolAddress(&p_ys, g_ys);
    cudaGetSymbolAddress(&p_gi, g_gi);
    float* ys = (float*)p_ys;
    float* gi = (float*)p_gi;

    const int gemm_smem  = (64 * 132 + 128 * 128) * 4;       // 99328 B
    const int qproj_smem = (128 * 129 + 128 * 20 + 18) * 4;  // 76360 B
    cudaFuncSetAttribute(gemm_fused,
        cudaFuncAttributeMaxDynamicSharedMemorySize, gemm_smem);
    cudaFuncSetAttribute(qproj_kernel,
        cudaFuncAttributeMaxDynamicSharedMemorySize, qproj_smem);

    // gi = relu(obs @ W_emb + b_emb) @ Wi + bi  (emb never touches DRAM)
    gemm_fused<<<TBROWS / 64, 128, gemm_smem>>>(obs, W_emb, b_emb, Wi, bi, gi);
    // GRU scan (R11; writes ys)
    scan_kernel<<<BATCH / 4, 384>>>(hidden, gi, dones, Wh, bhn, hfinal, ys);
    // q = ys @ W_out + b_out
    qproj_kernel<<<TBROWS / 128, 128, qproj_smem>>>(ys, W_out, b_out, q);
}

// round 16
// speedup vs baseline: 1.1007x; 1.1007x over previous
#include <cuda_runtime.h>
#include <cuda_bf16.h>
#include <cstdint>

#define T_STEPS 512
#define BATCH   512
#define HID     128
#define ACT     18
#define TBROWS  (T_STEPS * BATCH)   // 262144

// Scratch (device globals: allocation is forbidden)
__device__ float g_ys[(size_t)TBROWS * HID];
__device__ float g_gi [(size_t)TBROWS * 3 * HID];
// emb in bf16 hi/lo (written by gemm1, read by gemm2); packed 2 bf16 per u32
__device__ __align__(16) uint32_t g_embh[(size_t)TBROWS * 64];
__device__ __align__(16) uint32_t g_embl[(size_t)TBROWS * 64];
// weight panels, bf16 hi/lo, [n][k] plain row-major (prep kernel fills)
__device__ __align__(16) unsigned short g_Wembt[2][16384];
__device__ __align__(16) unsigned short g_Wit[3][2][16384];

typedef unsigned long long u64;

__device__ __forceinline__ u64 pk2(float x) {
    u64 d; asm("mov.b64 %0, {%1,%1};" : "=l"(d) : "f"(x)); return d;
}
__device__ __forceinline__ u64 pk2two(float a, float b) {
    u64 d; asm("mov.b64 %0, {%1,%2};" : "=l"(d) : "f"(a), "f"(b)); return d;
}
__device__ __forceinline__ void fma2(u64 &c, u64 a, u64 b) {
    asm("fma.rn.f32x2 %0, %1, %2, %3;" : "=l"(c) : "l"(a), "l"(b), "l"(c));
}
__device__ __forceinline__ u64 mul2(u64 a, u64 b) {
    u64 d; asm("mul.rn.f32x2 %0, %1, %2;" : "=l"(d) : "l"(a), "l"(b)); return d;
}
__device__ __forceinline__ float2 unpk(u64 v) {
    float2 f; asm("mov.b64 {%0,%1}, %2;" : "=f"(f.x), "=f"(f.y) : "l"(v)); return f;
}
__device__ __forceinline__ void cp_async16(uint32_t dst, const void* src) {
    asm volatile("cp.async.ca.shared.global [%0], [%1], 16;" :: "r"(dst), "l"(src));
}

// mma.sync m16n8k8 bf16, fp32 accum: ONE (row,k-pair) position per register.
// a0 = A[gid][2t,2t+1], a1 = A[gid+8][2t,2t+1], b0 = B[2t,2t+1][gid].
__device__ __forceinline__ void mma16808(float* d, uint32_t a0, uint32_t a1,
                                         uint32_t b0) {
    asm volatile(
        "mma.sync.aligned.m16n8k8.row.col.f32.bf16.bf16.f32 "
        "{%0,%1,%2,%3}, {%4,%5}, {%6}, {%0,%1,%2,%3};"
        : "+f"(d[0]), "+f"(d[1]), "+f"(d[2]), "+f"(d[3])
        : "r"(a0), "r"(a1), "r"(b0));
}

// ---------------------------------------------------------------------------
// prep: W_emb / Wi -> bf16 hi/lo panels in [n][k] layout
// ---------------------------------------------------------------------------
__global__ void prep_kernel(const float* __restrict__ W_emb,
                            const float* __restrict__ Wi)
{
    int idx = blockIdx.x * 256 + threadIdx.x;   // 0..65535
    float v; unsigned short *hi, *lo; int n, k;
    if (idx < 16384) {
        k = idx >> 7; n = idx & 127;
        v = W_emb[k * 128 + n];
        hi = g_Wembt[0]; lo = g_Wembt[1];
    } else {
        int j = idx - 16384, ch = j >> 14, r = j & 16383;
        k = r >> 7; n = r & 127;
        v = Wi[(size_t)k * 384 + ch * 128 + n];
        hi = g_Wit[ch][0]; lo = g_Wit[ch][1];
    }
    __nv_bfloat16 h = __float2bfloat16(v);
    __nv_bfloat16 l = __float2bfloat16(v - __bfloat162float(h));
    hi[n * 128 + k] = *(unsigned short*)&h;
    lo[n * 128 + k] = *(unsigned short*)&l;
}

// ---------------------------------------------------------------------------
// Shared smem layout (u32 words): Ah[64][68], Al[64][68], Bh[128][68],
// Bl[128][68]. Pitch 68 words (row stride mod 32 = 4 -> conflict-free).
// Words pack bf16 (k even = low half, k odd = high half).
// ---------------------------------------------------------------------------
#define PW   68
#define S_AH 0
#define S_AL 4352
#define S_BH 8704
#define S_BL 17408
#define S_TOTW 26112          // 104448 bytes

// per-warp 32x32 tile mainloop over K=128 (16 k8 steps), bf16x3 accumulation
__device__ __forceinline__ void mma_mainloop(
    const uint32_t* __restrict__ smw, int M0, int N0, int lr, int lw,
    float acc[2][4][4])
{
    const uint32_t* Ah = smw + S_AH;
    const uint32_t* Al = smw + S_AL;
    const uint32_t* Bh = smw + S_BH;
    const uint32_t* Bl = smw + S_BL;
    #pragma unroll
    for (int ks = 0; ks < 16; ++ks) {
        const int kw = ks * 4 + lw;       // word -> k = {2kw, 2kw+1}
        uint32_t ah[2][2], al[2][2], bh[4], bl[4];
        #pragma unroll
        for (int mt = 0; mt < 2; ++mt) {
            const uint32_t* ba = Ah + (M0 + mt * 16 + lr) * PW + kw;
            ah[mt][0] = ba[0];            // row gid,   k pair
            ah[mt][1] = ba[8 * PW];       // row gid+8, k pair
            const uint32_t* bal = Al + (M0 + mt * 16 + lr) * PW + kw;
            al[mt][0] = bal[0];
            al[mt][1] = bal[8 * PW];
        }
        #pragma unroll
        for (int nt = 0; nt < 4; ++nt) {
            bh[nt] = Bh[(N0 + nt * 8 + lr) * PW + kw];
            bl[nt] = Bl[(N0 + nt * 8 + lr) * PW + kw];
        }
        #pragma unroll
        for (int mt = 0; mt < 2; ++mt)
            #pragma unroll
            for (int nt = 0; nt < 4; ++nt) {
                mma16808(acc[mt][nt], ah[mt][0], ah[mt][1], bh[nt]);
                mma16808(acc[mt][nt], ah[mt][0], ah[mt][1], bl[nt]);
                mma16808(acc[mt][nt], al[mt][0], al[mt][1], bh[nt]);
            }
    }
}

// gemm1: emb = relu(obs @ W_emb + b_emb) -> g_embh/g_embl (bf16 hi/lo)
__global__ __launch_bounds__(256, 2) void gemm1_mma(
    const float* __restrict__ obs, const float* __restrict__ b_emb)
{
    extern __shared__ uint32_t smw[];
    const int tid = threadIdx.x, lane = tid & 31, wid = tid >> 5;
    const int m0g = blockIdx.x * 64;

    // B: W_emb hi/lo panels (gmem [n][k] u16 -> smem pitch 68)
    {
        const uint4* sh = (const uint4*)g_Wembt[0];
        const uint4* sl = (const uint4*)g_Wembt[1];
        for (int i = tid; i < 2048; i += 256) {
            int n = i >> 4, j = i & 15;
            *(uint4*)(smw + S_BH + n * PW + j * 4) = sh[i];
            *(uint4*)(smw + S_BL + n * PW + j * 4) = sl[i];
        }
    }
    // A: obs fp32 -> bf16 hi/lo.  FULL row = 64 words (128 k values):
    // 64 rows x 64 words = 4096 items.  (R14/R15 bug: covered only half.)
    for (int i = tid; i < 4096; i += 256) {
        int row = i >> 6, pc = i & 63;
        float2 v = *(const float2*)(obs + (size_t)(m0g + row) * 128 + pc * 2);
        __nv_bfloat162 h = __floats2bfloat162_rn(v.x, v.y);
        __nv_bfloat162 l = __floats2bfloat162_rn(v.x - __bfloat162float(h.x),
                                                 v.y - __bfloat162float(h.y));
        smw[S_AH + row * PW + pc] = *(uint32_t*)&h;
        smw[S_AL + row * PW + pc] = *(uint32_t*)&l;
    }
    __syncthreads();

    const int M0 = (wid >> 2) * 32, N0 = (wid & 3) * 32;
    const int lr = lane >> 2, lw = lane & 3;
    float acc[2][4][4] = {};
    mma_mainloop(smw, M0, N0, lr, lw, acc);

    #pragma unroll
    for (int mt = 0; mt < 2; ++mt) {
        const int row0 = m0g + M0 + mt * 16 + lr;
        #pragma unroll
        for (int nt = 0; nt < 4; ++nt) {
            const int col = N0 + nt * 8 + 2 * lw;
            const int widx = col >> 1;
            float b0v = __ldg(b_emb + col), b1v = __ldg(b_emb + col + 1);
            float v0 = fmaxf(acc[mt][nt][0] + b0v, 0.0f);
            float v1 = fmaxf(acc[mt][nt][1] + b1v, 0.0f);
            float v2 = fmaxf(acc[mt][nt][2] + b0v, 0.0f);
            float v3 = fmaxf(acc[mt][nt][3] + b1v, 0.0f);
            __nv_bfloat162 h01 = __floats2bfloat162_rn(v0, v1);
            __nv_bfloat162 l01 = __floats2bfloat162_rn(
                v0 - __bfloat162float(h01.x), v1 - __bfloat162float(h01.y));
            g_embh[(size_t)row0 * 64 + widx] = *(uint32_t*)&h01;
            g_embl[(size_t)row0 * 64 + widx] = *(uint32_t*)&l01;
            __nv_bfloat162 h23 = __floats2bfloat162_rn(v2, v3);
            __nv_bfloat162 l23 = __floats2bfloat162_rn(
                v2 - __bfloat162float(h23.x), v3 - __bfloat162float(h23.y));
            g_embh[(size_t)(row0 + 8) * 64 + widx] = *(uint32_t*)&h23;
            g_embl[(size_t)(row0 + 8) * 64 + widx] = *(uint32_t*)&l23;
        }
    }
}

// gemm2: gi[:, chunk] = emb @ Wi_chunk + bi_chunk   (grid.y = chunk)
__global__ __launch_bounds__(256, 2) void gemm2_mma(
    const float* __restrict__ bi, float* __restrict__ gi)
{
    extern __shared__ uint32_t smw[];
    const int tid = threadIdx.x, lane = tid & 31, wid = tid >> 5;
    const int m0g = blockIdx.x * 64;
    const int ch  = blockIdx.y;
    const int n0g = ch * 128;

    {
        const uint4* sh = (const uint4*)g_Wit[ch][0];
        const uint4* sl = (const uint4*)g_Wit[ch][1];
        for (int i = tid; i < 2048; i += 256) {
            int n = i >> 4, j = i & 15;
            *(uint4*)(smw + S_BH + n * PW + j * 4) = sh[i];
            *(uint4*)(smw + S_BL + n * PW + j * 4) = sl[i];
        }
    }
    // A: emb bf16 hi/lo straight copy (16 uint4 per row = 64 words)
    {
        const uint4* sh = (const uint4*)(g_embh + (size_t)m0g * 64);
        const uint4* sl = (const uint4*)(g_embl + (size_t)m0g * 64);
        for (int i = tid; i < 1024; i += 256) {
            int row = i >> 4, j = i & 15;
            *(uint4*)(smw + S_AH + row * PW + j * 4) = sh[i];
            *(uint4*)(smw + S_AL + row * PW + j * 4) = sl[i];
        }
    }
    __syncthreads();

    const int M0 = (wid >> 2) * 32, N0 = (wid & 3) * 32;
    const int lr = lane >> 2, lw = lane & 3;
    float acc[2][4][4] = {};
    mma_mainloop(smw, M0, N0, lr, lw, acc);

    #pragma unroll
    for (int mt = 0; mt < 2; ++mt) {
        const int row0 = m0g + M0 + mt * 16 + lr;
        #pragma unroll
        for (int nt = 0; nt < 4; ++nt) {
            const int col = N0 + nt * 8 + 2 * lw;
            float b0v = __ldg(bi + n0g + col), b1v = __ldg(bi + n0g + col + 1);
            *(float2*)(gi + (size_t)row0 * 384 + n0g + col) =
                make_float2(acc[mt][nt][0] + b0v, acc[mt][nt][1] + b1v);
            *(float2*)(gi + (size_t)(row0 + 8) * 384 + n0g + col) =
                make_float2(acc[mt][nt][2] + b0v, acc[mt][nt][3] + b1v);
        }
    }
}

// ---------------------------------------------------------------------------
// Scan (R11 — unchanged): 128 CTAs x 384 threads, packed-pair gates.
// ---------------------------------------------------------------------------
__device__ __forceinline__ float sigf(float x) {
    return __fdividef(1.0f, 1.0f + __expf(-x));
}
__device__ __forceinline__ float tanhfast(float x) {
    return __fdividef(2.0f, 1.0f + __expf(-2.0f * x)) - 1.0f;
}

__global__ __launch_bounds__(384, 1) void scan_kernel(
    const float* __restrict__ hidden, const float* __restrict__ gi_all,
    const int* __restrict__ dones,
    const float* __restrict__ Wh, const float* __restrict__ bhn,
    float* __restrict__ hfinal, float* __restrict__ ys)
{
    __shared__ float4 h4_s[128];
    __shared__ u64    gh01_s[384];
    __shared__ u64    gh23_s[384];
    __shared__ u64    bhn2_s[128];
    __shared__ u64    maskp_s[T_STEPS * 2];
    __shared__ float  gi_s[2][1536];

    const int tid = threadIdx.x;
    const int b0  = blockIdx.x * 4;

    const uint32_t gi_smem = (uint32_t)__cvta_generic_to_shared(&gi_s[0][0])
                             + (uint32_t)tid * 16u;
    const float* gi_src = gi_all + (size_t)b0 * 384 + tid * 4;

    cp_async16(gi_smem, gi_src);
    asm volatile("cp.async.commit_group;");

    float w[128];
    #pragma unroll
    for (int k = 0; k < 128; ++k)
        w[k] = Wh[(size_t)k * 384 + tid];

    if (tid < 128) bhn2_s[tid] = pk2(bhn[tid]);
    for (int i = tid; i < T_STEPS * 2; i += 384) {
        int t = i >> 1, p = i & 1;
        float m0_ = dones[t * BATCH + b0 + 2 * p]     ? 0.0f : 1.0f;
        float m1_ = dones[t * BATCH + b0 + 2 * p + 1] ? 0.0f : 1.0f;
        maskp_s[i] = pk2two(m0_, m1_);
    }
    for (int idx = tid; idx < 512; idx += 384) {
        int r = idx >> 7, i = idx & 127;
        ((float*)&h4_s[i])[r] = hidden[(size_t)(b0 + r) * 128 + i];
    }
    __syncthreads();

    const u64 NEG1 = pk2two(-1.0f, -1.0f);

    for (int t = 0; t < T_STEPS; ++t) {
        if (t + 1 < T_STEPS) {
            cp_async16(gi_smem + (((t + 1) & 1) ? 6144u : 0u),
                       gi_src + (size_t)(t + 1) * (BATCH * 384));
            asm volatile("cp.async.commit_group;");
        }

        u64 a01 = 0ull, a23 = 0ull;
        #pragma unroll
        for (int k = 0; k < 128; ++k) {
            ulonglong2 hv = *(const ulonglong2*)&h4_s[k];
            u64 wd = pk2(w[k]);
            fma2(a01, hv.x, wd);
            fma2(a23, hv.y, wd);
        }
        gh01_s[tid] = a01;
        gh23_s[tid] = a23;

        if (t + 1 < T_STEPS) {
            asm volatile("cp.async.wait_group 1;");
        } else {
            asm volatile("cp.async.wait_group 0;");
        }
        __syncthreads();   // (A)

        if (tid < 256) {
            const int p = tid >> 7;
            const int i = tid & 127;
            const u64* ghb = p ? gh23_s : gh01_s;
            const u64 mkp = maskp_s[t * 2 + p];

            u64 ghr = ghb[i];
            u64 ghz = ghb[128 + i];
            u64 ghn = ghb[256 + i];

            const float* gb0 = gi_s[t & 1] + (2 * p) * 384;
            const float* gb1 = gb0 + 384;
            u64 xr = pk2two(gb0[i],       gb1[i]);        fma2(xr, ghr, mkp);
            u64 xz = pk2two(gb0[128 + i], gb1[128 + i]);  fma2(xz, ghz, mkp);
            u64 gn = pk2two(gb0[256 + i], gb1[256 + i]);
            u64 t0 = bhn2_s[i];                           fma2(t0, ghn, mkp);

            float2 fr = unpk(xr);
            float2 fz = unpk(xz);
            u64 rp = pk2two(sigf(fr.x), sigf(fr.y));
            u64 zp = pk2two(sigf(fz.x), sigf(fz.y));

            u64 xn = gn; fma2(xn, rp, t0);
            float2 fn = unpk(xn);
            u64 np = pk2two(tanhfast(fn.x), tanhfast(fn.y));

            u64* hp = (u64*)(((char*)&h4_s[i]) + p * 8);
            u64 hm = mul2(*hp, mkp);
            u64 d  = hm; fma2(d, np, NEG1);
            u64 hn = np; fma2(hn, zp, d);
            *hp = hn;

            float2 fh = unpk(hn);
            float* yp = ys + ((size_t)t * BATCH + b0 + 2 * p) * 128 + i;
            yp[0]   = fh.x;
            yp[128] = fh.y;
        }
        __syncthreads();   // (B)
    }

    for (int idx = tid; idx < 512; idx += 384) {
        int r = idx >> 7, i = idx & 127;
        hfinal[(size_t)(b0 + r) * 128 + i] = ((float*)&h4_s[i])[r];
    }
}

// ---------------------------------------------------------------------------
// q projection (clock canary — byte-identical to R4/R11).
// ---------------------------------------------------------------------------
__global__ __launch_bounds__(128, 2) void qproj_kernel(
    const float* __restrict__ ys, const float* __restrict__ Wo,
    const float* __restrict__ bo, float* __restrict__ q)
{
    extern __shared__ float sm[];
    float* As   = sm;                 // [128][129]
    float* Wo_s = sm + 128 * 129;     // [128][20]
    float* bo_s = Wo_s + 128 * 20;    // [18]

    const int tid = threadIdx.x;
    const size_t m0 = (size_t)blockIdx.x * 128;

    for (int i = tid; i < 4096; i += 128) {
        int m = i >> 5, kv = (i & 31) << 2;
        float4 v = *(const float4*)(ys + (m0 + m) * 128 + kv);
        float* d = As + m * 129 + kv;
        d[0] = v.x; d[1] = v.y; d[2] = v.z; d[3] = v.w;
    }
    for (int i = tid; i < 128 * 18; i += 128)
        Wo_s[(i / 18) * 20 + (i % 18)] = Wo[i];
    if (tid < 18) bo_s[tid] = bo[tid];
    __syncthreads();

    u64 acc[9];
    #pragma unroll
    for (int p = 0; p < 9; ++p) acc[p] = pk2two(bo_s[2 * p], bo_s[2 * p + 1]);

    const float* ap = As + tid * 129;
    #pragma unroll 4
    for (int k = 0; k < 128; ++k) {
        u64 hd = pk2(ap[k]);
        const u64* wrow = (const u64*)(Wo_s + k * 20);
        #pragma unroll
        for (int p = 0; p < 9; ++p) fma2(acc[p], hd, wrow[p]);
    }

    float* qp = q + (m0 + tid) * ACT;
    #pragma unroll
    for (int p = 0; p < 9; ++p) {
        float2 f = unpk(acc[p]);
        *(float2*)(qp + 2 * p) = f;
    }
}

// ---------------------------------------------------------------------------
extern "C" void kernel_launch(void* const* d_in, const int* in_sizes, int n_in,
                              void* d_out, int out_size)
{
    const float* hidden = (const float*)d_in[0];
    const float* obs    = (const float*)d_in[1];
    const int*   dones  = (const int*)d_in[2];
    const float* W_emb  = (const float*)d_in[3];
    const float* b_emb  = (const float*)d_in[4];
    const float* Wi     = (const float*)d_in[5];
    const float* bi     = (const float*)d_in[6];
    const float* Wh     = (const float*)d_in[7];
    const float* bhn    = (const float*)d_in[8];
    const float* W_out  = (const float*)d_in[9];
    const float* b_out  = (const float*)d_in[10];

    float* out    = (float*)d_out;
    float* hfinal = out;                        // [512, 128]
    float* q      = out + (size_t)BATCH * HID;  // [512, 512, 18]

    void *p_ys, *p_gi;
    cudaGetSymbolAddress(&p_ys, g_ys);
    cudaGetSymbolAddress(&p_gi, g_gi);
    float* ys = (float*)p_ys;
    float* gi = (float*)p_gi;

    const int mma_smem   = S_TOTW * 4;                       // 104448 B
    const int qproj_smem = (128 * 129 + 128 * 20 + 18) * 4;  // 76360 B
    cudaFuncSetAttribute(gemm1_mma,
        cudaFuncAttributeMaxDynamicSharedMemorySize, mma_smem);
    cudaFuncSetAttribute(gemm2_mma,
        cudaFuncAttributeMaxDynamicSharedMemorySize, mma_smem);
    cudaFuncSetAttribute(qproj_kernel,
        cudaFuncAttributeMaxDynamicSharedMemorySize, qproj_smem);

    // weights -> bf16 hi/lo panels
    prep_kernel<<<256, 256>>>(W_emb, Wi);
    // emb = relu(obs@W_emb + b_emb)  (bf16x3 tensor-core k8, writes hi/lo)
    gemm1_mma<<<TBROWS / 64, 256, mma_smem>>>(obs, b_emb);
    // gi = emb@Wi + bi
    gemm2_mma<<<dim3(TBROWS / 64, 3), 256, mma_smem>>>(bi, gi);
    // GRU scan (R11)
    scan_kernel<<<BATCH / 4, 384>>>(hidden, gi, dones, Wh, bhn, hfinal, ys);
    // q = ys @ W_out + b_out
    qproj_kernel<<<TBROWS / 128, 128, qproj_smem>>>(ys, W_out, b_out, q);
}

// round 17
// speedup vs baseline: 1.3320x; 1.2101x over previous
#include <cuda_runtime.h>
#include <cuda_bf16.h>
#include <cstdint>

#define T_STEPS 512
#define BATCH   512
#define HID     128
#define ACT     18
#define TBROWS  (T_STEPS * BATCH)   // 262144

// Scratch (device globals: allocation is forbidden)
__device__ float g_ys[(size_t)TBROWS * HID];
__device__ float g_gi [(size_t)TBROWS * 3 * HID];
__device__ __align__(16) uint32_t g_embh[(size_t)TBROWS * 64];
__device__ __align__(16) uint32_t g_embl[(size_t)TBROWS * 64];
// weight panels, bf16 hi/lo, [n][k] row-major
__device__ __align__(16) unsigned short g_Wembt[2][16384];
__device__ __align__(16) unsigned short g_Wit[3][2][16384];
__device__ __align__(16) unsigned short g_Whh[49152];   // Wh^T hi [384][128]
__device__ __align__(16) unsigned short g_Whl[49152];   // Wh^T lo

typedef unsigned long long u64;

__device__ __forceinline__ u64 pk2two(float a, float b) {
    u64 d; asm("mov.b64 %0, {%1,%2};" : "=l"(d) : "f"(a), "f"(b)); return d;
}
__device__ __forceinline__ u64 pk2(float x) {
    u64 d; asm("mov.b64 %0, {%1,%1};" : "=l"(d) : "f"(x)); return d;
}
__device__ __forceinline__ void fma2(u64 &c, u64 a, u64 b) {
    asm("fma.rn.f32x2 %0, %1, %2, %3;" : "=l"(c) : "l"(a), "l"(b), "l"(c));
}
__device__ __forceinline__ float2 unpk(u64 v) {
    float2 f; asm("mov.b64 {%0,%1}, %2;" : "=f"(f.x), "=f"(f.y) : "l"(v)); return f;
}

// mma.sync m16n8k8 bf16, fp32 accum (mapping proven in R16)
__device__ __forceinline__ void mma16808(float* d, uint32_t a0, uint32_t a1,
                                         uint32_t b0) {
    asm volatile(
        "mma.sync.aligned.m16n8k8.row.col.f32.bf16.bf16.f32 "
        "{%0,%1,%2,%3}, {%4,%5}, {%6}, {%0,%1,%2,%3};"
        : "+f"(d[0]), "+f"(d[1]), "+f"(d[2]), "+f"(d[3])
        : "r"(a0), "r"(a1), "r"(b0));
}

__device__ __forceinline__ float bflo(uint32_t w) {
    __nv_bfloat162 t = *(__nv_bfloat162*)&w; return __bfloat162float(t.x);
}
__device__ __forceinline__ float bfhi(uint32_t w) {
    __nv_bfloat162 t = *(__nv_bfloat162*)&w; return __bfloat162float(t.y);
}

// ---------------------------------------------------------------------------
// prep: W_emb / Wi / Wh -> bf16 hi/lo panels in [n][k] layout
// ---------------------------------------------------------------------------
__global__ void prep_kernel(const float* __restrict__ W_emb,
                            const float* __restrict__ Wi,
                            const float* __restrict__ Wh)
{
    int idx = blockIdx.x * 256 + threadIdx.x;   // 0..114687
    if (idx >= 114688) return;
    float v; unsigned short *hi, *lo; int n, k, kn;
    if (idx < 16384) {
        k = idx >> 7; n = idx & 127;
        v = W_emb[k * 128 + n];
        hi = g_Wembt[0]; lo = g_Wembt[1]; kn = 128;
    } else if (idx < 65536) {
        int j = idx - 16384, ch = j >> 14, r = j & 16383;
        k = r >> 7; n = r & 127;
        v = Wi[(size_t)k * 384 + ch * 128 + n];
        hi = g_Wit[ch][0]; lo = g_Wit[ch][1]; kn = 128;
    } else {
        int j = idx - 65536;        // 0..49151 : Wh [128][384]
        k = j / 384; n = j % 384;
        v = Wh[(size_t)k * 384 + n];
        hi = g_Whh; lo = g_Whl; kn = 128;
    }
    __nv_bfloat16 h = __float2bfloat16(v);
    __nv_bfloat16 l = __float2bfloat16(v - __bfloat162float(h));
    hi[n * kn + k] = *(unsigned short*)&h;
    lo[n * kn + k] = *(unsigned short*)&l;
}

// ---------------------------------------------------------------------------
// GEMM smem layout (u32 words): Ah[64][68], Al[64][68], Bh[128][68], Bl[128][68]
// ---------------------------------------------------------------------------
#define PW   68
#define S_AH 0
#define S_AL 4352
#define S_BH 8704
#define S_BL 17408
#define S_TOTW 26112          // 104448 bytes

__device__ __forceinline__ void mma_mainloop(
    const uint32_t* __restrict__ smw, int M0, int N0, int lr, int lw,
    float acc[2][4][4])
{
    const uint32_t* Ah = smw + S_AH;
    const uint32_t* Al = smw + S_AL;
    const uint32_t* Bh = smw + S_BH;
    const uint32_t* Bl = smw + S_BL;
    #pragma unroll
    for (int ks = 0; ks < 16; ++ks) {
        const int kw = ks * 4 + lw;
        uint32_t ah[2][2], al[2][2], bh[4], bl[4];
        #pragma unroll
        for (int mt = 0; mt < 2; ++mt) {
            const uint32_t* ba = Ah + (M0 + mt * 16 + lr) * PW + kw;
            ah[mt][0] = ba[0];
            ah[mt][1] = ba[8 * PW];
            const uint32_t* bal = Al + (M0 + mt * 16 + lr) * PW + kw;
            al[mt][0] = bal[0];
            al[mt][1] = bal[8 * PW];
        }
        #pragma unroll
        for (int nt = 0; nt < 4; ++nt) {
            bh[nt] = Bh[(N0 + nt * 8 + lr) * PW + kw];
            bl[nt] = Bl[(N0 + nt * 8 + lr) * PW + kw];
        }
        #pragma unroll
        for (int mt = 0; mt < 2; ++mt)
            #pragma unroll
            for (int nt = 0; nt < 4; ++nt) {
                mma16808(acc[mt][nt], ah[mt][0], ah[mt][1], bh[nt]);
                mma16808(acc[mt][nt], ah[mt][0], ah[mt][1], bl[nt]);
                mma16808(acc[mt][nt], al[mt][0], al[mt][1], bh[nt]);
            }
    }
}

// gemm1: emb = relu(obs @ W_emb + b_emb) -> g_embh/g_embl
__global__ __launch_bounds__(256, 2) void gemm1_mma(
    const float* __restrict__ obs, const float* __restrict__ b_emb)
{
    extern __shared__ uint32_t smw[];
    const int tid = threadIdx.x, lane = tid & 31, wid = tid >> 5;
    const int m0g = blockIdx.x * 64;

    {
        const uint4* sh = (const uint4*)g_Wembt[0];
        const uint4* sl = (const uint4*)g_Wembt[1];
        for (int i = tid; i < 2048; i += 256) {
            int n = i >> 4, j = i & 15;
            *(uint4*)(smw + S_BH + n * PW + j * 4) = sh[i];
            *(uint4*)(smw + S_BL + n * PW + j * 4) = sl[i];
        }
    }
    for (int i = tid; i < 4096; i += 256) {
        int row = i >> 6, pc = i & 63;
        float2 v = *(const float2*)(obs + (size_t)(m0g + row) * 128 + pc * 2);
        __nv_bfloat162 h = __floats2bfloat162_rn(v.x, v.y);
        __nv_bfloat162 l = __floats2bfloat162_rn(v.x - __bfloat162float(h.x),
                                                 v.y - __bfloat162float(h.y));
        smw[S_AH + row * PW + pc] = *(uint32_t*)&h;
        smw[S_AL + row * PW + pc] = *(uint32_t*)&l;
    }
    __syncthreads();

    const int M0 = (wid >> 2) * 32, N0 = (wid & 3) * 32;
    const int lr = lane >> 2, lw = lane & 3;
    float acc[2][4][4] = {};
    mma_mainloop(smw, M0, N0, lr, lw, acc);

    #pragma unroll
    for (int mt = 0; mt < 2; ++mt) {
        const int row0 = m0g + M0 + mt * 16 + lr;
        #pragma unroll
        for (int nt = 0; nt < 4; ++nt) {
            const int col = N0 + nt * 8 + 2 * lw;
            const int widx = col >> 1;
            float b0v = __ldg(b_emb + col), b1v = __ldg(b_emb + col + 1);
            float v0 = fmaxf(acc[mt][nt][0] + b0v, 0.0f);
            float v1 = fmaxf(acc[mt][nt][1] + b1v, 0.0f);
            float v2 = fmaxf(acc[mt][nt][2] + b0v, 0.0f);
            float v3 = fmaxf(acc[mt][nt][3] + b1v, 0.0f);
            __nv_bfloat162 h01 = __floats2bfloat162_rn(v0, v1);
            __nv_bfloat162 l01 = __floats2bfloat162_rn(
                v0 - __bfloat162float(h01.x), v1 - __bfloat162float(h01.y));
            g_embh[(size_t)row0 * 64 + widx] = *(uint32_t*)&h01;
            g_embl[(size_t)row0 * 64 + widx] = *(uint32_t*)&l01;
            __nv_bfloat162 h23 = __floats2bfloat162_rn(v2, v3);
            __nv_bfloat162 l23 = __floats2bfloat162_rn(
                v2 - __bfloat162float(h23.x), v3 - __bfloat162float(h23.y));
            g_embh[(size_t)(row0 + 8) * 64 + widx] = *(uint32_t*)&h23;
            g_embl[(size_t)(row0 + 8) * 64 + widx] = *(uint32_t*)&l23;
        }
    }
}

// gemm2: gi[:, chunk] = emb @ Wi_chunk + bi_chunk
__global__ __launch_bounds__(256, 2) void gemm2_mma(
    const float* __restrict__ bi, float* __restrict__ gi)
{
    extern __shared__ uint32_t smw[];
    const int tid = threadIdx.x, lane = tid & 31, wid = tid >> 5;
    const int m0g = blockIdx.x * 64;
    const int ch  = blockIdx.y;
    const int n0g = ch * 128;

    {
        const uint4* sh = (const uint4*)g_Wit[ch][0];
        const uint4* sl = (const uint4*)g_Wit[ch][1];
        for (int i = tid; i < 2048; i += 256) {
            int n = i >> 4, j = i & 15;
            *(uint4*)(smw + S_BH + n * PW + j * 4) = sh[i];
            *(uint4*)(smw + S_BL + n * PW + j * 4) = sl[i];
        }
    }
    {
        const uint4* sh = (const uint4*)(g_embh + (size_t)m0g * 64);
        const uint4* sl = (const uint4*)(g_embl + (size_t)m0g * 64);
        for (int i = tid; i < 1024; i += 256) {
            int row = i >> 4, j = i & 15;
            *(uint4*)(smw + S_AH + row * PW + j * 4) = sh[i];
            *(uint4*)(smw + S_AL + row * PW + j * 4) = sl[i];
        }
    }
    __syncthreads();

    const int M0 = (wid >> 2) * 32, N0 = (wid & 3) * 32;
    const int lr = lane >> 2, lw = lane & 3;
    float acc[2][4][4] = {};
    mma_mainloop(smw, M0, N0, lr, lw, acc);

    #pragma unroll
    for (int mt = 0; mt < 2; ++mt) {
        const int row0 = m0g + M0 + mt * 16 + lr;
        #pragma unroll
        for (int nt = 0; nt < 4; ++nt) {
            const int col = N0 + nt * 8 + 2 * lw;
            float b0v = __ldg(bi + n0g + col), b1v = __ldg(bi + n0g + col + 1);
            *(float2*)(gi + (size_t)row0 * 384 + n0g + col) =
                make_float2(acc[mt][nt][0] + b0v, acc[mt][nt][1] + b1v);
            *(float2*)(gi + (size_t)(row0 + 8) * 384 + n0g + col) =
                make_float2(acc[mt][nt][2] + b0v, acc[mt][nt][3] + b1v);
        }
    }
}

// ---------------------------------------------------------------------------
// HMMA scan: 64 CTAs x 512 threads, 8 batch rows/CTA.
// Wh bf16 hi/lo panels in smem (pitch 66); hi B-fragments hoisted to regs.
// Warp w owns cols {8w, 128+8w, 256+8w} -> all 3 gates in C fragments; gates
// computed in-register, 2 barriers/step. h kept as bf16 hi/lo in smem.
// ---------------------------------------------------------------------------
__device__ __forceinline__ float sigf(float x) {
    return __fdividef(1.0f, 1.0f + __expf(-x));
}
__device__ __forceinline__ float tanhfast(float x) {
    return __fdividef(2.0f, 1.0f + __expf(-2.0f * x)) - 1.0f;
}

#define WPITCH 66
#define SCW_WHH 0            // [384][66] u32
#define SCW_WHL 25344
#define SCW_HH  50688        // [8][66] u32
#define SCW_HL  51216
#define SCW_BHN 51744        // 128 floats
#define SCW_TOT 51872        // words -> 207488 bytes

__global__ __launch_bounds__(512, 1) void scan_mma(
    const float* __restrict__ hidden, const float* __restrict__ gi_all,
    const int* __restrict__ dones, const float* __restrict__ bhn,
    float* __restrict__ hfinal, float* __restrict__ ys)
{
    extern __shared__ uint32_t sw[];
    uint32_t* whh = sw + SCW_WHH;
    uint32_t* whl = sw + SCW_WHL;
    uint32_t* hh  = sw + SCW_HH;
    uint32_t* hl  = sw + SCW_HL;
    float* bhn_s  = (float*)(sw + SCW_BHN);

    const int tid = threadIdx.x, lane = tid & 31, w = tid >> 5;
    const int lr = lane >> 2, lw = lane & 3;
    const int b0 = blockIdx.x * 8;

    // stage Wh panels (gmem pitch 64 words -> smem pitch 66)
    {
        const uint32_t* gh32 = (const uint32_t*)g_Whh;
        const uint32_t* gl32 = (const uint32_t*)g_Whl;
        for (int i = tid; i < 24576; i += 512) {
            int n = i >> 6, kw = i & 63;
            whh[n * WPITCH + kw] = gh32[i];
            whl[n * WPITCH + kw] = gl32[i];
        }
    }
    if (tid < 128) bhn_s[tid] = bhn[tid];
    // h init (8 rows x 64 words)
    if (tid < 512) {
        int i = tid;
        if (i < 512) {
            int r = i >> 6, kw = i & 63;
            float2 v = *(const float2*)(hidden + (size_t)(b0 + r) * 128 + kw * 2);
            __nv_bfloat162 h2 = __floats2bfloat162_rn(v.x, v.y);
            __nv_bfloat162 l2 = __floats2bfloat162_rn(
                v.x - __bfloat162float(h2.x), v.y - __bfloat162float(h2.y));
            hh[r * WPITCH + kw] = *(uint32_t*)&h2;
            hl[r * WPITCH + kw] = *(uint32_t*)&l2;
        }
    }
    __syncthreads();

    // hoist hi B fragments (static Wh)
    const int N0r = 8 * w, N0z = 128 + 8 * w, N0n = 256 + 8 * w;
    uint32_t bhr[16], bhz[16], bhq[16];
    #pragma unroll
    for (int ks = 0; ks < 16; ++ks) {
        int kwo = ks * 4 + lw;
        bhr[ks] = whh[(N0r + lr) * WPITCH + kwo];
        bhz[ks] = whh[(N0z + lr) * WPITCH + kwo];
        bhq[ks] = whh[(N0n + lr) * WPITCH + kwo];
    }

    const int colg = 8 * w + 2 * lw;        // even col in [0,128)
    const int hword = lr * WPITCH + 4 * w + lw;
    const float bq0 = bhn_s[colg], bq1 = bhn_s[colg + 1];

    for (int t = 0; t < T_STEPS; ++t) {
        // prefetch gi + mask (consumed after barrier A)
        const size_t grow = ((size_t)t * BATCH + b0 + lr) * 384;
        float2 gir = *(const float2*)(gi_all + grow + colg);
        float2 giz = *(const float2*)(gi_all + grow + 128 + colg);
        float2 gin = *(const float2*)(gi_all + grow + 256 + colg);
        float mk = dones[t * BATCH + b0 + lr] ? 0.0f : 1.0f;

        float cr[4] = {0, 0, 0, 0}, cz[4] = {0, 0, 0, 0}, cq[4] = {0, 0, 0, 0};
        #pragma unroll
        for (int ks = 0; ks < 16; ++ks) {
            int kwo = ks * 4 + lw;
            uint32_t a0h = hh[lr * WPITCH + kwo];
            uint32_t a0l = hl[lr * WPITCH + kwo];
            uint32_t blr = whl[(N0r + lr) * WPITCH + kwo];
            uint32_t blz = whl[(N0z + lr) * WPITCH + kwo];
            uint32_t blq = whl[(N0n + lr) * WPITCH + kwo];
            mma16808(cr, a0h, 0u, bhr[ks]);
            mma16808(cr, a0h, 0u, blr);
            mma16808(cr, a0l, 0u, bhr[ks]);
            mma16808(cz, a0h, 0u, bhz[ks]);
            mma16808(cz, a0h, 0u, blz);
            mma16808(cz, a0l, 0u, bhz[ks]);
            mma16808(cq, a0h, 0u, bhq[ks]);
            mma16808(cq, a0h, 0u, blq);
            mma16808(cq, a0l, 0u, bhq[ks]);
        }
        // read h_old BEFORE barrier (still old value, no race)
        uint32_t hwh = hh[hword], hwl = hl[hword];
        __syncthreads();   // (A) all reads of hh/hl done

        // gates for items (row lr, cols colg, colg+1)
        float h0 = bflo(hwh) + bflo(hwl);
        float h1 = bfhi(hwh) + bfhi(hwl);
        float r0 = sigf(gir.x + mk * cr[0]);
        float z0 = sigf(giz.x + mk * cz[0]);
        float n0 = tanhfast(gin.x + r0 * (mk * cq[0] + bq0));
        float hn0 = (1.0f - z0) * n0 + z0 * (h0 * mk);
        float r1 = sigf(gir.y + mk * cr[1]);
        float z1 = sigf(giz.y + mk * cz[1]);
        float n1 = tanhfast(gin.y + r1 * (mk * cq[1] + bq1));
        float hn1 = (1.0f - z1) * n1 + z1 * (h1 * mk);

        __nv_bfloat162 nh = __floats2bfloat162_rn(hn0, hn1);
        __nv_bfloat162 nl = __floats2bfloat162_rn(
            hn0 - __bfloat162float(nh.x), hn1 - __bfloat162float(nh.y));
        hh[hword] = *(uint32_t*)&nh;
        hl[hword] = *(uint32_t*)&nl;
        *(float2*)(ys + ((size_t)t * BATCH + b0 + lr) * 128 + colg) =
            make_float2(hn0, hn1);
        __syncthreads();   // (B) new h visible for next step
    }

    // h_final
    for (int i = tid; i < 1024; i += 512) {
        int r = i >> 7, c = i & 127;
        uint32_t wh_ = hh[r * WPITCH + (c >> 1)];
        uint32_t wl_ = hl[r * WPITCH + (c >> 1)];
        float v = (c & 1) ? (bfhi(wh_) + bfhi(wl_)) : (bflo(wh_) + bflo(wl_));
        hfinal[(size_t)(b0 + r) * 128 + c] = v;
    }
}

// ---------------------------------------------------------------------------
// q projection (clock canary — byte-identical to R4/R11).
// ---------------------------------------------------------------------------
__global__ __launch_bounds__(128, 2) void qproj_kernel(
    const float* __restrict__ ys, const float* __restrict__ Wo,
    const float* __restrict__ bo, float* __restrict__ q)
{
    extern __shared__ float sm[];
    float* As   = sm;                 // [128][129]
    float* Wo_s = sm + 128 * 129;     // [128][20]
    float* bo_s = Wo_s + 128 * 20;    // [18]

    const int tid = threadIdx.x;
    const size_t m0 = (size_t)blockIdx.x * 128;

    for (int i = tid; i < 4096; i += 128) {
        int m = i >> 5, kv = (i & 31) << 2;
        float4 v = *(const float4*)(ys + (m0 + m) * 128 + kv);
        float* d = As + m * 129 + kv;
        d[0] = v.x; d[1] = v.y; d[2] = v.z; d[3] = v.w;
    }
    for (int i = tid; i < 128 * 18; i += 128)
        Wo_s[(i / 18) * 20 + (i % 18)] = Wo[i];
    if (tid < 18) bo_s[tid] = bo[tid];
    __syncthreads();

    u64 acc[9];
    #pragma unroll
    for (int p = 0; p < 9; ++p) acc[p] = pk2two(bo_s[2 * p], bo_s[2 * p + 1]);

    const float* ap = As + tid * 129;
    #pragma unroll 4
    for (int k = 0; k < 128; ++k) {
        u64 hd = pk2(ap[k]);
        const u64* wrow = (const u64*)(Wo_s + k * 20);
        #pragma unroll
        for (int p = 0; p < 9; ++p) fma2(acc[p], hd, wrow[p]);
    }

    float* qp = q + (m0 + tid) * ACT;
    #pragma unroll
    for (int p = 0; p < 9; ++p) {
        float2 f = unpk(acc[p]);
        *(float2*)(qp + 2 * p) = f;
    }
}

// ---------------------------------------------------------------------------
extern "C" void kernel_launch(void* const* d_in, const int* in_sizes, int n_in,
                              void* d_out, int out_size)
{
    const float* hidden = (const float*)d_in[0];
    const float* obs    = (const float*)d_in[1];
    const int*   dones  = (const int*)d_in[2];
    const float* W_emb  = (const float*)d_in[3];
    const float* b_emb  = (const float*)d_in[4];
    const float* Wi     = (const float*)d_in[5];
    const float* bi     = (const float*)d_in[6];
    const float* Wh     = (const float*)d_in[7];
    const float* bhn    = (const float*)d_in[8];
    const float* W_out  = (const float*)d_in[9];
    const float* b_out  = (const float*)d_in[10];

    float* out    = (float*)d_out;
    float* hfinal = out;                        // [512, 128]
    float* q      = out + (size_t)BATCH * HID;  // [512, 512, 18]

    void *p_ys, *p_gi;
    cudaGetSymbolAddress(&p_ys, g_ys);
    cudaGetSymbolAddress(&p_gi, g_gi);
    float* ys = (float*)p_ys;
    float* gi = (float*)p_gi;

    const int mma_smem   = S_TOTW * 4;                       // 104448 B
    const int scan_smem  = SCW_TOT * 4;                      // 207488 B
    const int qproj_smem = (128 * 129 + 128 * 20 + 18) * 4;  // 76360 B
    cudaFuncSetAttribute(gemm1_mma,
        cudaFuncAttributeMaxDynamicSharedMemorySize, mma_smem);
    cudaFuncSetAttribute(gemm2_mma,
        cudaFuncAttributeMaxDynamicSharedMemorySize, mma_smem);
    cudaFuncSetAttribute(scan_mma,
        cudaFuncAttributeMaxDynamicSharedMemorySize, scan_smem);
    cudaFuncSetAttribute(qproj_kernel,
        cudaFuncAttributeMaxDynamicSharedMemorySize, qproj_smem);

    // weights -> bf16 hi/lo panels (incl. Wh)
    prep_kernel<<<448, 256>>>(W_emb, Wi, Wh);
    // emb = relu(obs@W_emb + b_emb)
    gemm1_mma<<<TBROWS / 64, 256, mma_smem>>>(obs, b_emb);
    // gi = emb@Wi + bi
    gemm2_mma<<<dim3(TBROWS / 64, 3), 256, mma_smem>>>(bi, gi);
    // GRU scan (HMMA bf16x3 matvec, in-register gates)
    scan_mma<<<BATCH / 8, 512, scan_smem>>>(hidden, gi, dones, bhn, hfinal, ys);
    // q = ys @ W_out + b_out
    qproj_kernel<<<TBROWS / 128, 128, qproj_smem>>>(ys, W_out, b_out, q);
}